// round 9
// baseline (speedup 1.0000x reference)
#include <cuda_runtime.h>
#include <cuda_bf16.h>
#include <stdint.h>

#define BS   16
#define MM   128
#define NA   8400
#define NC   80
#define KTOP 13
#define CAP  1024
#define EPS7 1e-7f
#define EPS9 1e-9f
#define FULL 0xffffffffu
#define CNT1 (1 << 20)   // packed claim increment: cnt in high bits, sum(m) low

// scratch (static device globals -- allowed)
__device__ int    g_cs  [BS * NA];    // packed: (cnt<<20) | sum_of_m
__device__ float  g_alsum[BS * NA];
__device__ float  g_ovsum[BS * NA];
__device__ unsigned long long g_cand[(size_t)BS * MM * CAP];
__device__ int    g_ccount[BS * MM];
__device__ float  g_pos_am[BS * MM];
__device__ float  g_pos_ov[BS * MM];
__device__ int    g_tgt[BS * NA];
__device__ float  g_al [BS * NA];
__device__ int    g_fglist[BS * NA];
__device__ int    g_multilist[BS * NA];
__device__ int    g_nfg;
__device__ int    g_nmulti;
__device__ float4 g_gtbox[BS * MM];   // gt box
__device__ float4 g_gtaux[BS * MM];   // {at1, mask, label(int bits), unused}

// ---------------------------------------------------------------------------
// CIoU (identical math to reference _ciou + clip>=0)
// ---------------------------------------------------------------------------
__device__ __forceinline__ float ciou_core(const float4 g, const float4 p,
                                           float at_g, float at_p)
{
    const float c4pi2 = 0.40528473456935108577f;  // 4/pi^2
    float w1 = g.z - g.x, h1 = g.w - g.y + EPS7;
    float w2 = p.z - p.x, h2 = p.w - p.y + EPS7;
    float iw = fminf(g.z, p.z) - fmaxf(g.x, p.x);
    float ih = fminf(g.w, p.w) - fmaxf(g.y, p.y);
    float inter = fmaxf(iw, 0.f) * fmaxf(ih, 0.f);
    float uni = w1 * h1 + w2 * h2 - inter + EPS7;
    float iou = inter / uni;
    float cw = fmaxf(g.z, p.z) - fminf(g.x, p.x);
    float ch = fmaxf(g.w, p.w) - fminf(g.y, p.y);
    float c2 = cw * cw + ch * ch + EPS7;
    float dx = p.x + p.z - g.x - g.z;
    float dy = p.y + p.w - g.y - g.w;
    float rho2 = (dx * dx + dy * dy) * 0.25f;
    float dat = at_p - at_g;
    float v = c4pi2 * dat * dat;
    float alpha = v / (v - iou + (1.f + EPS7));
    return fmaxf(iou - (rho2 / c2 + v * alpha), 0.f);
}
__device__ __forceinline__ float ciou_hg(const float4 g, const float4 p, float at_g)
{
    return ciou_core(g, p, at_g, atanf((p.z - p.x) / (p.w - p.y + EPS7)));
}
__device__ __forceinline__ float dmin_xy(const float4 g, float ax, float ay)
{
    return fminf(fminf(ax - g.x, ay - g.y), fminf(g.z - ax, g.w - ay));
}

// ---------------------------------------------------------------------------
// KZ (side stream): zero the per-anchor accumulators
// ---------------------------------------------------------------------------
__global__ __launch_bounds__(256) void kz_zero()
{
    int i = blockIdx.x * blockDim.x + threadIdx.x;
    if (i < BS * NA) {
        g_cs[i] = 0;
        g_alsum[i] = 0.f;
        g_ovsum[i] = 0.f;
    }
}

// ---------------------------------------------------------------------------
// K0p: small prep -- GT table, per-row counters, global counters
// ---------------------------------------------------------------------------
__global__ __launch_bounds__(256) void k0p(
    const int*   __restrict__ gt_labels,
    const float* __restrict__ gt_bboxes,
    const float* __restrict__ mask_gt)
{
    int i = blockIdx.x * blockDim.x + threadIdx.x;
    if (i < BS * MM) {
        g_ccount[i] = 0;
        g_pos_am[i] = 0.f; g_pos_ov[i] = 0.f;
        float4 g = reinterpret_cast<const float4*>(gt_bboxes)[i];
        g_gtbox[i] = g;
        float4 aux;
        aux.x = atanf((g.z - g.x) / (g.w - g.y + EPS7));
        aux.y = mask_gt[i];
        aux.z = __int_as_float(gt_labels[i]);
        aux.w = 0.f;
        g_gtaux[i] = aux;
    }
    if (i == 0) { g_nfg = 0; g_nmulti = 0; }
}

// ---------------------------------------------------------------------------
// K1a: one THREAD per (row, rect-cell). Positive align metrics pushed into
// per-row candidate buffers as packed keys.
// ---------------------------------------------------------------------------
__global__ __launch_bounds__(256) void k1a(
    const float* __restrict__ pd_scores,
    const float* __restrict__ pd_bboxes,
    const int*   __restrict__ gt_labels,
    const float* __restrict__ gt_bboxes,
    const float* __restrict__ mask_gt)
{
    int row = blockIdx.y;                  // b*MM + m
    if (mask_gt[row] <= 0.f) return;
    int t = blockIdx.x * 256 + threadIdx.x;

    float4 g = reinterpret_cast<const float4*>(gt_bboxes)[row];

    int ix0s[3], iy0s[3], ws[3];
    int tot = 0, t0 = 0, t1 = 0;
    #pragma unroll
    for (int ks = 0; ks < 3; ++ks) {
        const int   n = (ks == 0) ? 80 : (ks == 1) ? 40 : 20;
        const float s = (ks == 0) ? 8.f : (ks == 1) ? 16.f : 32.f;
        int ix0 = max(0,     (int)floorf(g.x / s - 0.5f));
        int ix1 = min(n - 1, (int)floorf(g.z / s - 0.5f) + 1);
        int iy0 = max(0,     (int)floorf(g.y / s - 0.5f));
        int iy1 = min(n - 1, (int)floorf(g.w / s - 0.5f) + 1);
        int w = max(ix1 - ix0 + 1, 0), h = max(iy1 - iy0 + 1, 0);
        ix0s[ks] = ix0; iy0s[ks] = iy0; ws[ks] = w;
        if (ks == 0) t0 = w * h;
        if (ks == 1) t1 = w * h;
        tot += w * h;
    }
    if (t >= tot) return;

    int ks, tc;
    if (t < t0)            { ks = 0; tc = t; }
    else if (t < t0 + t1)  { ks = 1; tc = t - t0; }
    else                   { ks = 2; tc = t - t0 - t1; }
    const int   n   = (ks == 0) ? 80 : (ks == 1) ? 40 : 20;
    const float s   = (ks == 0) ? 8.f : (ks == 1) ? 16.f : 32.f;
    const int   off = (ks == 0) ? 0 : (ks == 1) ? 6400 : 8000;
    int ix = ix0s[ks] + tc % ws[ks];
    int iy = iy0s[ks] + tc / ws[ks];
    float ax = (ix + 0.5f) * s, ay = (iy + 0.5f) * s;
    if (dmin_xy(g, ax, ay) <= EPS9) return;

    int b = row >> 7;
    int idx = off + iy * n + ix;
    float at1 = atanf((g.z - g.x) / (g.w - g.y + EPS7));
    float4 p = reinterpret_cast<const float4*>(pd_bboxes)[(size_t)b * NA + idx];
    float ov = ciou_hg(g, p, at1);
    if (ov <= 0.f) return;
    int lbl = gt_labels[row];
    float sc = pd_scores[((size_t)b * NA + idx) * NC + lbl];
    float o2 = ov * ov;
    float al = sc * (o2 * o2 * o2);
    if (al <= 0.f) return;

    int slot = atomicAdd(&g_ccount[row], 1);
    if (slot < CAP)
        g_cand[(size_t)row * CAP + slot] =
            ((unsigned long long)__float_as_uint(al) << 32) |
            (unsigned)(0x7fffffff - idx);
}

// ---------------------------------------------------------------------------
// K1b: one WARP per row: top-13 over candidate keys (value desc, index asc),
// claims carry al + ov.
// ---------------------------------------------------------------------------
__global__ __launch_bounds__(256) void k1b(
    const float* __restrict__ pd_bboxes,
    const float* __restrict__ gt_bboxes,
    const float* __restrict__ mask_gt)
{
    int wid = threadIdx.x >> 5, lane = threadIdx.x & 31;
    int row = blockIdx.x * 8 + wid;
    if (row >= BS * MM) return;
    if (mask_gt[row] <= 0.f) return;
    int b = row >> 7, m = row & 127;

    int ncand = min(g_ccount[row], CAP);
    const unsigned long long* cp = g_cand + (size_t)row * CAP;

    unsigned long long keys[KTOP];
    #pragma unroll
    for (int j = 0; j < KTOP; ++j) keys[j] = 0ull;

    for (int j = lane; j < ncand; j += 32) {
        unsigned long long ck = cp[j];
        if (ck > keys[KTOP - 1]) {
            #pragma unroll
            for (int q = 0; q < KTOP; ++q) {
                unsigned long long kq = keys[q];
                if (ck > kq) { keys[q] = ck; ck = kq; }
            }
        }
    }

    int   mysel = -1;
    float myval = 0.f;
    int qsel = 0;
    #pragma unroll 1
    for (int it = 0; it < KTOP; ++it) {
        unsigned long long k = keys[0];
        #pragma unroll
        for (int d = 16; d; d >>= 1) {
            unsigned long long o = __shfl_xor_sync(FULL, k, d);
            if (o > k) k = o;
        }
        if ((unsigned)(k >> 32) == 0u) break;
        if (lane == qsel) {
            mysel = 0x7fffffff - (int)(k & 0xffffffffu);
            myval = __uint_as_float((unsigned)(k >> 32));
        }
        qsel++;
        if (keys[0] == k) {
            #pragma unroll
            for (int j = 0; j < KTOP - 1; ++j) keys[j] = keys[j + 1];
            keys[KTOP - 1] = 0ull;
        }
    }

    float4 g = reinterpret_cast<const float4*>(gt_bboxes)[row];

    if (lane < qsel) {
        float at1 = atanf((g.z - g.x) / (g.w - g.y + EPS7));
        float4 p = reinterpret_cast<const float4*>(pd_bboxes)[(size_t)b * NA + mysel];
        float ov = ciou_hg(g, p, at1);
        atomicAdd(&g_cs   [b * NA + mysel], CNT1 | m);
        atomicAdd(&g_alsum[b * NA + mysel], myval);
        atomicAdd(&g_ovsum[b * NA + mysel], ov);
    }

    // zero-fill (rare): smallest-index zero-valued anchors of the full row
    if (qsel < KTOP) {
        int sarr[KTOP];
        for (int t = 0; t < qsel; ++t)
            sarr[t] = __shfl_sync(FULL, mysel, t);
        if (lane == 0) {
            float at1 = atanf((g.z - g.x) / (g.w - g.y + EPS7));
            const float4* pbb = reinterpret_cast<const float4*>(pd_bboxes) + (size_t)b * NA;
            int need = KTOP - qsel;
            int j = 0;
            while (need > 0 && j < 8 * KTOP) {
                bool ispos = false;
                for (int t = 0; t < qsel; ++t) if (sarr[t] == j) { ispos = true; break; }
                if (!ispos) {
                    int ix = j % 80, iy = j / 80;   // j small -> scale-8 grid
                    float ax = (ix + 0.5f) * 8.f, ay = (iy + 0.5f) * 8.f;
                    if (dmin_xy(g, ax, ay) > EPS9) {
                        float ov = ciou_hg(g, pbb[j], at1);
                        atomicAdd(&g_cs   [b * NA + j], CNT1 | m);
                        atomicAdd(&g_ovsum[b * NA + j], ov);
                    }
                    need--;
                }
                j++;
            }
        }
    }
}

// ---------------------------------------------------------------------------
// K3a: per (b,a). cnt<=1 fully resolved with carried sums; lists use
// warp-aggregated atomics (one counter atomic per warp, not per thread).
// ---------------------------------------------------------------------------
__global__ __launch_bounds__(256) void k3a(float* __restrict__ out)
{
    int idx = blockIdx.x * blockDim.x + threadIdx.x;   // grid == BS*NA exactly
    int lane = threadIdx.x & 31;
    int b = idx / NA;

    int cs = g_cs[idx];
    int cnt = cs >> 20;
    bool is_multi = cnt > 1;
    bool is_fg1   = cnt == 1;

    unsigned mmask = __ballot_sync(FULL, is_multi);
    if (mmask) {
        int leader = __ffs(mmask) - 1;
        int base = 0;
        if (lane == leader) base = atomicAdd(&g_nmulti, __popc(mmask));
        base = __shfl_sync(FULL, base, leader);
        if (is_multi)
            g_multilist[base + __popc(mmask & ((1u << lane) - 1))] = idx;
    }
    unsigned fmask = __ballot_sync(FULL, is_fg1);
    if (fmask) {
        int leader = __ffs(fmask) - 1;
        int base = 0;
        if (lane == leader) base = atomicAdd(&g_nfg, __popc(fmask));
        base = __shfl_sync(FULL, base, leader);
        if (is_fg1)
            g_fglist[base + __popc(fmask & ((1u << lane) - 1))] = idx;
    }
    if (is_multi) return;                  // outputs written by k3bF

    int fg = cnt, tgt = 0;
    float al = 0.f;
    if (is_fg1) {
        tgt = cs & 0xfffff;
        al  = g_alsum[idx];
        float ovm = g_ovsum[idx];
        int row = b * MM + tgt;
        atomicMax((unsigned int*)&g_pos_am[row], __float_as_uint(al));
        atomicMax((unsigned int*)&g_pos_ov[row], __float_as_uint(ovm));
    }
    g_tgt[idx] = tgt;
    g_al [idx] = al;

    int grow = b * MM + tgt;
    int lbl = max(__float_as_int(g_gtaux[grow].z), 0);
    float4 bx = g_gtbox[grow];
    float* o_lab = out;
    float* o_box = out + (size_t)BS * NA;
    float* o_fg  = out + (size_t)BS * NA * (5 + NC);
    float* o_tg  = o_fg + (size_t)BS * NA;
    o_lab[idx] = (float)lbl;
    reinterpret_cast<float4*>(o_box)[idx] = bx;
    o_fg[idx] = fg ? 1.f : 0.f;
    o_tg[idx] = (float)tgt;
}

// ---------------------------------------------------------------------------
// K3bF: one BLOCK (128 thr) per multi entry: thread m computes masked CIoU,
// block-reduce packed key (val<<32 | (MM-1-m)), thread 0 finishes the entry.
// ---------------------------------------------------------------------------
__global__ __launch_bounds__(128) void k3bF(
    const float* __restrict__ pd_scores,
    const float* __restrict__ pd_bboxes,
    const float* __restrict__ anc,
    float* __restrict__ out)
{
    __shared__ unsigned long long swk[4];
    int nm = g_nmulti;
    int m = threadIdx.x;
    int lane = m & 31, wid = m >> 5;

    for (int e = blockIdx.x; e < nm; e += gridDim.x) {
        int idx = g_multilist[e];
        int b = idx / NA, a = idx - b * NA;
        float4 p  = reinterpret_cast<const float4*>(pd_bboxes)[idx];
        float2 an = reinterpret_cast<const float2*>(anc)[a];
        float at2 = atanf((p.z - p.x) / (p.w - p.y + EPS7));

        int row = b * MM + m;
        float4 aux = g_gtaux[row];
        float v = 0.f;
        if (aux.y > 0.f) {
            float4 gg = g_gtbox[row];
            if (dmin_xy(gg, an.x, an.y) > EPS9)
                v = ciou_core(gg, p, aux.x, at2);
        }
        unsigned long long key =
            ((unsigned long long)__float_as_uint(v) << 32) |
            (unsigned)(MM - 1 - m);
        #pragma unroll
        for (int d = 16; d; d >>= 1) {
            unsigned long long o = __shfl_xor_sync(FULL, key, d);
            if (o > key) key = o;
        }
        if (lane == 0) swk[wid] = key;
        __syncthreads();

        if (m == 0) {
            unsigned long long k = swk[0];
            #pragma unroll
            for (int w2 = 1; w2 < 4; ++w2) if (swk[w2] > k) k = swk[w2];
            int tgt = MM - 1 - (int)(k & 0xffffffffu);
            float ovm = __uint_as_float((unsigned)(k >> 32));
            int rw = b * MM + tgt;
            int lbl = __float_as_int(g_gtaux[rw].z);
            float al = 0.f;
            if (ovm > 0.f) {
                float sc = pd_scores[((size_t)b * NA + a) * NC + lbl];
                float o2 = ovm * ovm;
                al = sc * (o2 * o2 * o2);
            }
            atomicMax((unsigned int*)&g_pos_am[rw], __float_as_uint(al));
            atomicMax((unsigned int*)&g_pos_ov[rw], __float_as_uint(ovm));
            g_tgt[idx] = tgt;
            g_al [idx] = al;
            int q = atomicAdd(&g_nfg, 1);
            g_fglist[q] = idx;

            float4 bx = g_gtbox[rw];
            float* o_lab = out;
            float* o_box = out + (size_t)BS * NA;
            float* o_fg  = out + (size_t)BS * NA * (5 + NC);
            float* o_tg  = o_fg + (size_t)BS * NA;
            o_lab[idx] = (float)max(lbl, 0);
            reinterpret_cast<float4*>(o_box)[idx] = bx;
            o_fg[idx] = 1.f;
            o_tg[idx] = (float)tgt;
        }
        __syncthreads();
    }
}

// ---------------------------------------------------------------------------
// K4: sparse nrm scatter over the compacted fg list (scores pre-zeroed)
// ---------------------------------------------------------------------------
__global__ __launch_bounds__(256) void k4_scatter(float* __restrict__ out)
{
    float* o_sc = out + (size_t)BS * NA * 5;
    int nfg = g_nfg;
    int stride = gridDim.x * blockDim.x;
    for (int i = blockIdx.x * blockDim.x + threadIdx.x; i < nfg; i += stride) {
        int idx = g_fglist[i];
        int b = idx / NA;
        int tgt = g_tgt[idx];
        int grow = b * MM + tgt;
        int lbl = max(__float_as_int(g_gtaux[grow].z), 0);
        float nrm = g_al[idx] * g_pos_ov[grow] / (g_pos_am[grow] + EPS9);
        o_sc[(size_t)idx * NC + lbl] = nrm;
    }
}

// ---------------------------------------------------------------------------
extern "C" void kernel_launch(void* const* d_in, const int* in_sizes, int n_in,
                              void* d_out, int out_size)
{
    const float* pd_scores = (const float*)d_in[0];
    const float* pd_bboxes = (const float*)d_in[1];
    const float* anc       = (const float*)d_in[2];
    const int*   gt_labels = (const int*)  d_in[3];
    const float* gt_bboxes = (const float*)d_in[4];
    const float* mask_gt   = (const float*)d_in[5];
    float* out = (float*)d_out;

    static cudaStream_t s2 = nullptr;
    static cudaEvent_t evFork = nullptr, evZ = nullptr, evJoin = nullptr;
    if (!s2) {
        cudaStreamCreateWithFlags(&s2, cudaStreamNonBlocking);
        cudaEventCreateWithFlags(&evFork, cudaEventDisableTiming);
        cudaEventCreateWithFlags(&evZ,    cudaEventDisableTiming);
        cudaEventCreateWithFlags(&evJoin, cudaEventDisableTiming);
    }

    float* o_sc = out + (size_t)BS * NA * 5;
    int n = BS * NA;

    // side stream: scratch zero (needed before k1b), then score memset (before k4)
    cudaEventRecord(evFork, 0);
    cudaStreamWaitEvent(s2, evFork, 0);
    kz_zero<<<(n + 255) / 256, 256, 0, s2>>>();
    cudaEventRecord(evZ, s2);
    cudaMemsetAsync(o_sc, 0, (size_t)BS * NA * NC * sizeof(float), s2);
    cudaEventRecord(evJoin, s2);

    // main stream
    k0p<<<(BS * MM + 255) / 256, 256>>>(gt_labels, gt_bboxes, mask_gt);
    k1a<<<dim3(5, BS * MM), 256>>>(pd_scores, pd_bboxes,
                                   gt_labels, gt_bboxes, mask_gt);
    cudaStreamWaitEvent(0, evZ, 0);        // g_cs/alsum/ovsum zeroed
    k1b<<<(BS * MM + 7) / 8, 256>>>(pd_bboxes, gt_bboxes, mask_gt);
    k3a<<<n / 256, 256>>>(out);
    k3bF<<<2048, 128>>>(pd_scores, pd_bboxes, anc, out);
    cudaStreamWaitEvent(0, evJoin, 0);     // score memset done
    k4_scatter<<<64, 256>>>(out);
}